// round 14
// baseline (speedup 1.0000x reference)
#include <cuda_runtime.h>
#include <cstdint>
#include <cstddef>

#define B4    4
#define NSEQ  4096
#define CDIM  1024
#define NH    16
#define HD    64
#define NBH   (B4*NH)
#define KVSPLIT 8

// device-global scratch (no runtime allocation)
static __device__ float g_x  [B4 * NSEQ * CDIM];   // tf32-rounded X
static __device__ float g_wk [CDIM * CDIM];        // tf32-rounded Wk
static __device__ float g_wv [CDIM * CDIM];        // tf32-rounded Wv
static __device__ float g_wo [CDIM * CDIM];        // tf32-rounded Wo
static __device__ float g_k  [NBH * NSEQ * HD];    // [B,H,N,D]
static __device__ float g_v  [NBH * NSEQ * HD];
static __device__ float g_kv [NBH * HD * HD];      // fp32, scaled
static __device__ float g_kvp[KVSPLIT * NBH * HD * HD];
static __device__ float g_r  [B4 * CDIM * CDIM];   // R[c][he], tf32-rounded
static __device__ float g_gt [B4 * CDIM * CDIM];   // Gt[co][c], tf32-rounded

__device__ __forceinline__ float tf32r(float x) {
    uint32_t u;
    asm("cvt.rna.tf32.f32 %0, %1;" : "=r"(u) : "f"(x));
    return __uint_as_float(u);
}
__device__ __forceinline__ uint32_t smem_u32(const void* p) {
    uint32_t a;
    asm("{ .reg .u64 t; cvta.to.shared.u64 t, %1; cvt.u32.u64 %0, t; }"
        : "=r"(a) : "l"(p));
    return a;
}
#define CP16(saddr, gptr) \
    asm volatile("cp.async.cg.shared.global [%0], [%1], 16;" :: "r"(saddr), "l"(gptr))
#define CP_COMMIT()  asm volatile("cp.async.commit_group;")
#define CP_WAIT1()   asm volatile("cp.async.wait_group 1;")
#define CP_WAIT0()   asm volatile("cp.async.wait_group 0;")

__device__ __forceinline__ void mma8(float c[4], const float a[4], const float b[2]) {
    const uint32_t* A  = reinterpret_cast<const uint32_t*>(a);
    const uint32_t* Bv = reinterpret_cast<const uint32_t*>(b);
    asm volatile(
        "mma.sync.aligned.m16n8k8.row.col.f32.tf32.tf32.f32 "
        "{%0,%1,%2,%3}, {%4,%5,%6,%7}, {%8,%9}, {%0,%1,%2,%3};\n"
        : "+f"(c[0]), "+f"(c[1]), "+f"(c[2]), "+f"(c[3])
        : "r"(A[0]), "r"(A[1]), "r"(A[2]), "r"(A[3]),
          "r"(Bv[0]), "r"(Bv[1]));
}

// ---------------------------------------------------------------------------
// prepass: tf32-round into device-global copies (R6-proven body)
// ---------------------------------------------------------------------------
__global__ __launch_bounds__(256, 1)
void round_tf32(const float* __restrict__ src, int which)
{
    float* dst = (which == 0) ? g_x
               : (which == 1) ? g_wk
               : (which == 2) ? g_wv : g_wo;
    const int i = blockIdx.x * 256 + threadIdx.x;
    float4 v = reinterpret_cast<const float4*>(src)[i];
    reinterpret_cast<float4*>(dst)[i] =
        make_float4(tf32r(v.x), tf32r(v.y), tf32r(v.z), tf32r(v.w));
}

// ---------------------------------------------------------------------------
// proj_kv: K/V projections (R6-proven proj2 MODE0 body; z selects Wk/Wv).
// C[m,n] = sum_k X[m,k]*W[n,k], scattered into g_k/g_v [B,H,N,D].
// grid (8, 128, 2), 256 threads, (256,2).
// ---------------------------------------------------------------------------
__global__ __launch_bounds__(256, 2)
void proj_kv()
{
    __shared__ float sA[2][128][20];
    __shared__ float sB[2][128][20];

    const int tid  = threadIdx.x;
    const int lane = tid & 31, warpId = tid >> 5;
    const int g  = lane >> 2, t = lane & 3;
    const int wm = warpId & 1, wn = warpId >> 1;
    const int n0 = blockIdx.x * 128;
    const int m0 = blockIdx.y * 128;
    const int z  = blockIdx.z;

    const float* A = (const float*)g_x;
    const float* W = (z == 0) ? (const float*)g_wk : (const float*)g_wv;

    const int lr  = tid >> 1;
    const int lco = (tid & 1) * 8;
    const float* gA = A + (size_t)(m0 + lr) * CDIM + lco;
    const float* gB = W + (size_t)(n0 + lr) * CDIM + lco;
    const uint32_t saA = smem_u32(&sA[0][lr][lco]);
    const uint32_t saB = smem_u32(&sB[0][lr][lco]);
    const uint32_t STG = 128 * 20 * 4;

    auto load_stage = [&](int s, int kt) {
        const float* pa = gA + kt * 16;
        const float* pb = gB + kt * 16;
        const uint32_t oa = saA + (uint32_t)s * STG;
        const uint32_t ob = saB + (uint32_t)s * STG;
        CP16(oa,      pa);
        CP16(oa + 16, pa + 4);
        CP16(ob,      pb);
        CP16(ob + 16, pb + 4);
        CP_COMMIT();
    };

    float acc[4][4][4];
#pragma unroll
    for (int a = 0; a < 4; ++a)
#pragma unroll
        for (int b = 0; b < 4; ++b)
#pragma unroll
            for (int c = 0; c < 4; ++c) acc[a][b][c] = 0.f;

    load_stage(0, 0);
    for (int kt = 0; kt < 64; ++kt) {
        const int cur = kt & 1;
        if (kt < 63) load_stage(cur ^ 1, kt + 1);
        if (kt < 63) CP_WAIT1(); else CP_WAIT0();
        __syncthreads();
#pragma unroll
        for (int ks = 0; ks < 2; ++ks) {
            const int kk = ks * 8;
            float af[4][4], bfr[4][2];
#pragma unroll
            for (int mi = 0; mi < 4; ++mi) {
                const int rm = wm * 64 + mi * 16 + g;
                af[mi][0] = sA[cur][rm][kk + t];
                af[mi][1] = sA[cur][rm + 8][kk + t];
                af[mi][2] = sA[cur][rm][kk + t + 4];
                af[mi][3] = sA[cur][rm + 8][kk + t + 4];
            }
#pragma unroll
            for (int ni = 0; ni < 4; ++ni) {
                const int cn = wn * 32 + ni * 8 + g;
                bfr[ni][0] = sB[cur][cn][kk + t];
                bfr[ni][1] = sB[cur][cn][kk + t + 4];
            }
#pragma unroll
            for (int mi = 0; mi < 4; ++mi)
#pragma unroll
                for (int ni = 0; ni < 4; ++ni)
                    mma8(acc[mi][ni], af[mi], bfr[ni]);
        }
        __syncthreads();
    }

    float* qkv = (z == 0) ? g_k : g_v;

#pragma unroll
    for (int mi = 0; mi < 4; ++mi) {
#pragma unroll
        for (int ni = 0; ni < 4; ++ni) {
            const int row = m0 + wm * 64 + mi * 16 + g;
            const int col = n0 + wn * 32 + ni * 8 + 2 * t;
            const int b = row >> 12, n = row & (NSEQ - 1);
            const int h = col >> 6,  d = col & (HD - 1);
            float* p = qkv + (((size_t)(b * NH + h) * NSEQ + n) * HD + d);
            *reinterpret_cast<float2*>(p) =
                make_float2(acc[mi][ni][0], acc[mi][ni][1]);
            *reinterpret_cast<float2*>(p + 8 * HD) =
                make_float2(acc[mi][ni][2], acc[mi][ni][3]);
        }
    }
}

// ---------------------------------------------------------------------------
// kv partial (R6-proven): kvp[split][bh] = sum_{n in split} k[n,d]*v[n,e]
// ---------------------------------------------------------------------------
__global__ __launch_bounds__(256, 1)
void kv_partial()
{
    __shared__ float sk[2][32][72];
    __shared__ float sv[2][32][72];
    const int bh = blockIdx.x;
    const int split = blockIdx.y;
    const int nt0 = split * 16;
    const float* Kp = g_k + (size_t)bh * NSEQ * HD;
    const float* Vp = g_v + (size_t)bh * NSEQ * HD;

    const int tid = threadIdx.x;
    const int lane = tid & 31, warpId = tid >> 5;
    const int g = lane >> 2, t = lane & 3;
    const int wm = warpId & 1, wn = warpId >> 1;
    const int lrow = tid >> 4;
    const int lc   = (tid & 15) * 4;

    float4 rk0, rk1, rv0, rv1;
    auto fetch = [&](int nt) {
        const size_t base = (size_t)(nt * 32 + lrow) * HD + lc;
        rk0 = *reinterpret_cast<const float4*>(Kp + base);
        rk1 = *reinterpret_cast<const float4*>(Kp + base + 16 * HD);
        rv0 = *reinterpret_cast<const float4*>(Vp + base);
        rv1 = *reinterpret_cast<const float4*>(Vp + base + 16 * HD);
    };
    auto cvt4 = [](float4 v) {
        return make_float4(tf32r(v.x), tf32r(v.y), tf32r(v.z), tf32r(v.w));
    };
    auto stage = [&](int bf) {
        *reinterpret_cast<float4*>(&sk[bf][lrow][lc])      = cvt4(rk0);
        *reinterpret_cast<float4*>(&sk[bf][lrow + 16][lc]) = cvt4(rk1);
        *reinterpret_cast<float4*>(&sv[bf][lrow][lc])      = cvt4(rv0);
        *reinterpret_cast<float4*>(&sv[bf][lrow + 16][lc]) = cvt4(rv1);
    };

    float acc[2][2][4];
#pragma unroll
    for (int a = 0; a < 2; ++a)
#pragma unroll
        for (int b = 0; b < 2; ++b)
#pragma unroll
            for (int c = 0; c < 4; ++c) acc[a][b][c] = 0.f;

    fetch(nt0); stage(0); __syncthreads();
    int buf = 0;
    for (int it = 0; it < 16; ++it) {
        if (it < 15) fetch(nt0 + it + 1);
#pragma unroll
        for (int ks = 0; ks < 4; ++ks) {
            const int kk = ks * 8;
            float af[2][4], bfr[2][2];
#pragma unroll
            for (int mi = 0; mi < 2; ++mi) {
                const int rd = wm * 32 + mi * 16 + g;
                af[mi][0] = sk[buf][kk + t][rd];
                af[mi][1] = sk[buf][kk + t][rd + 8];
                af[mi][2] = sk[buf][kk + t + 4][rd];
                af[mi][3] = sk[buf][kk + t + 4][rd + 8];
            }
#pragma unroll
            for (int ni = 0; ni < 2; ++ni) {
                const int ce = wn * 16 + ni * 8 + g;
                bfr[ni][0] = sv[buf][kk + t][ce];
                bfr[ni][1] = sv[buf][kk + t + 4][ce];
            }
#pragma unroll
            for (int mi = 0; mi < 2; ++mi)
#pragma unroll
                for (int ni = 0; ni < 2; ++ni)
                    mma8(acc[mi][ni], af[mi], bfr[ni]);
        }
        if (it < 15) { stage(buf ^ 1); __syncthreads(); buf ^= 1; }
    }

    float* O = g_kvp + ((size_t)split * NBH + bh) * HD * HD;
#pragma unroll
    for (int mi = 0; mi < 2; ++mi)
#pragma unroll
        for (int ni = 0; ni < 2; ++ni) {
            const int d0 = wm * 32 + mi * 16 + g;
            const int e  = wn * 16 + ni * 8 + 2 * t;
            *reinterpret_cast<float2*>(O + (size_t)d0 * HD + e) =
                make_float2(acc[mi][ni][0], acc[mi][ni][1]);
            *reinterpret_cast<float2*>(O + (size_t)(d0 + 8) * HD + e) =
                make_float2(acc[mi][ni][2], acc[mi][ni][3]);
        }
}

__global__ __launch_bounds__(256, 1)
void kv_reduce()
{
    const int i = blockIdx.x * 256 + threadIdx.x;   // float4 index
    float4 s = make_float4(0.f, 0.f, 0.f, 0.f);
#pragma unroll
    for (int sp = 0; sp < KVSPLIT; ++sp) {
        float4 v = *reinterpret_cast<const float4*>(g_kvp + (size_t)sp * NBH * HD * HD + i * 4);
        s.x += v.x; s.y += v.y; s.z += v.z; s.w += v.w;
    }
    *reinterpret_cast<float4*>(g_kv + (size_t)i * 4) =
        make_float4(s.x * 0.125f, s.y * 0.125f, s.z * 0.125f, s.w * 0.125f);
}

// ---------------------------------------------------------------------------
// r_build (scalar SIMT, spill-proof: one scalar accumulator, no arrays):
// R_b[c, h*64+e] = sum_d Wq[h*64+d, c] * kv_bh[d, e]  (Wq exact fp32)
// grid (256 c-chunks of 4, 16 h, 4 b), 256 threads: thread = (cl 0..3, e 0..63)
// ---------------------------------------------------------------------------
__global__ __launch_bounds__(256, 1)
void r_build(const float* __restrict__ Wq)
{
    __shared__ float skv[64][64];
    __shared__ float swq[4][64];
    const int b  = blockIdx.z, h = blockIdx.y;
    const int c0 = blockIdx.x * 4;
    const int tid = threadIdx.x;
    const int cl = tid >> 6;        // 0..3
    const int e  = tid & 63;        // 0..63

    const float* KV = g_kv + (size_t)(b * NH + h) * HD * HD;
    for (int i = tid; i < 4096; i += 256)
        skv[i >> 6][i & 63] = KV[i];
    // swq[cl][d] = Wq[(h*64+d)*CDIM + c0+cl]
    swq[cl][e] = Wq[(size_t)(h * 64 + e) * CDIM + c0 + cl];
    __syncthreads();

    float acc = 0.f;
    for (int d = 0; d < 64; ++d)
        acc += swq[cl][d] * skv[d][e];

    g_r[(size_t)b * CDIM * CDIM + (size_t)(c0 + cl) * CDIM + h * 64 + e] = tf32r(acc);
}

// ---------------------------------------------------------------------------
// gemm_b: R6-proven proj2 body, compile-time K=1024 and strides; per-b pointers
// via compile-time-selected globals (same ternary pattern R6 proved).
// MODE 0: Gt_b[co][c] = sum_he Wo[co,he]*R_b[c,he], tf32-rounded. grid (8,8,4)
// MODE 1: out_b[n][co] = sum_c X_b[n,c]*Gt_b[co,c] + bo[co].       grid (8,32,4)
// ---------------------------------------------------------------------------
template<int MODE>
__global__ __launch_bounds__(256, 2)
void gemm_b(const float* __restrict__ bias, float* __restrict__ outp)
{
    __shared__ float sA[2][128][20];
    __shared__ float sB[2][128][20];

    const int tid  = threadIdx.x;
    const int lane = tid & 31, warpId = tid >> 5;
    const int g  = lane >> 2, t = lane & 3;
    const int wm = warpId & 1, wn = warpId >> 1;
    const int n0 = blockIdx.x * 128;
    const int m0 = blockIdx.y * 128;
    const int z  = blockIdx.z;

    const size_t M1c = (size_t)CDIM * CDIM;
    const size_t MXc = (size_t)NSEQ * CDIM;

    const float* A = (MODE == 0) ? (const float*)g_wo
                                 : (const float*)g_x + (size_t)z * MXc;
    const float* B = (MODE == 0) ? (const float*)g_r  + (size_t)z * M1c
                                 : (const float*)g_gt + (size_t)z * M1c;
    float*       C = (MODE == 0) ? (float*)g_gt + (size_t)z * M1c
                                 : outp + (size_t)z * MXc;

    const int lr  = tid >> 1;
    const int lco = (tid & 1) * 8;
    const float* gA = A + (size_t)(m0 + lr) * CDIM + lco;
    const float* gB = B + (size_t)(n0 + lr) * CDIM + lco;
    const uint32_t saA = smem_u32(&sA[0][lr][lco]);
    const uint32_t saB = smem_u32(&sB[0][lr][lco]);
    const uint32_t STG = 128 * 20 * 4;

    auto load_stage = [&](int s, int kt) {
        const float* pa = gA + kt * 16;
        const float* pb = gB + kt * 16;
        const uint32_t oa = saA + (uint32_t)s * STG;
        const uint32_t ob = saB + (uint32_t)s * STG;
        CP16(oa,      pa);
        CP16(oa + 16, pa + 4);
        CP16(ob,      pb);
        CP16(ob + 16, pb + 4);
        CP_COMMIT();
    };

    float acc[4][4][4];
#pragma unroll
    for (int a = 0; a < 4; ++a)
#pragma unroll
        for (int b = 0; b < 4; ++b)
#pragma unroll
            for (int c = 0; c < 4; ++c) acc[a][b][c] = 0.f;

    load_stage(0, 0);
    for (int kt = 0; kt < 64; ++kt) {
        const int cur = kt & 1;
        if (kt < 63) load_stage(cur ^ 1, kt + 1);
        if (kt < 63) CP_WAIT1(); else CP_WAIT0();
        __syncthreads();
#pragma unroll
        for (int ks = 0; ks < 2; ++ks) {
            const int kk = ks * 8;
            float af[4][4], bfr[4][2];
#pragma unroll
            for (int mi = 0; mi < 4; ++mi) {
                const int rm = wm * 64 + mi * 16 + g;
                af[mi][0] = sA[cur][rm][kk + t];
                af[mi][1] = sA[cur][rm + 8][kk + t];
                af[mi][2] = sA[cur][rm][kk + t + 4];
                af[mi][3] = sA[cur][rm + 8][kk + t + 4];
            }
#pragma unroll
            for (int ni = 0; ni < 4; ++ni) {
                const int cn = wn * 32 + ni * 8 + g;
                bfr[ni][0] = sB[cur][cn][kk + t];
                bfr[ni][1] = sB[cur][cn][kk + t + 4];
            }
#pragma unroll
            for (int mi = 0; mi < 4; ++mi)
#pragma unroll
                for (int ni = 0; ni < 4; ++ni)
                    mma8(acc[mi][ni], af[mi], bfr[ni]);
        }
        __syncthreads();
    }

#pragma unroll
    for (int mi = 0; mi < 4; ++mi) {
#pragma unroll
        for (int ni = 0; ni < 4; ++ni) {
            const int row = m0 + wm * 64 + mi * 16 + g;
            const int col = n0 + wn * 32 + ni * 8 + 2 * t;
            float* p0 = C + (size_t)row * CDIM + col;
            float* p1 = C + (size_t)(row + 8) * CDIM + col;
            if (MODE == 0) {
                *reinterpret_cast<float2*>(p0) =
                    make_float2(tf32r(acc[mi][ni][0]), tf32r(acc[mi][ni][1]));
                *reinterpret_cast<float2*>(p1) =
                    make_float2(tf32r(acc[mi][ni][2]), tf32r(acc[mi][ni][3]));
            } else {
                const float b0v = bias[col], b1v = bias[col + 1];
                *reinterpret_cast<float2*>(p0) =
                    make_float2(acc[mi][ni][0] + b0v, acc[mi][ni][1] + b1v);
                *reinterpret_cast<float2*>(p1) =
                    make_float2(acc[mi][ni][2] + b0v, acc[mi][ni][3] + b1v);
            }
        }
    }
}

extern "C" void kernel_launch(void* const* d_in, const int* in_sizes, int n_in,
                              void* d_out, int out_size)
{
    (void)in_sizes; (void)n_in; (void)out_size;
    const float* x  = (const float*)d_in[0];
    const float* Wq = (const float*)d_in[1];
    const float* Wk = (const float*)d_in[2];
    const float* Wv = (const float*)d_in[3];
    const float* Wo = (const float*)d_in[4];
    const float* bo = (const float*)d_in[5];
    float* out = (float*)d_out;

    // prepass: tf32-round X, Wk, Wv, Wo (Wq stays exact fp32 for r_build)
    round_tf32<<<(B4 * NSEQ * CDIM / 4) / 256, 256>>>(x, 0);
    round_tf32<<<(CDIM * CDIM / 4) / 256, 256>>>(Wk, 1);
    round_tf32<<<(CDIM * CDIM / 4) / 256, 256>>>(Wv, 2);
    round_tf32<<<(CDIM * CDIM / 4) / 256, 256>>>(Wo, 3);

    // K and V projections (R6-proven body)
    proj_kv<<<dim3(CDIM / 128, (B4 * NSEQ) / 128, 2), 256>>>();

    // kv = 0.125 * k^T v per (b,h)  (R6-proven split-8 + reduce)
    kv_partial<<<dim3(NBH, KVSPLIT), 256>>>();
    kv_reduce<<<(NBH * HD * HD / 4) / 256, 256>>>();

    // R_b[c,he] = sum_d Wq[hd,c]*kv[d,e]  (exact fp32, rounded store)
    r_build<<<dim3(256, NH, B4), 256>>>(Wq);

    // Gt_b = Wo (contract he) R_b^T ; then out = X Gt^T + bo
    gemm_b<0><<<dim3(8, 8, B4), 256>>>(nullptr, nullptr);
    gemm_b<1><<<dim3(8, 32, B4), 256>>>(bo, out);
}

// round 15
// speedup vs baseline: 1.0013x; 1.0013x over previous
#include <cuda_runtime.h>
#include <cstdint>
#include <cstddef>

#define B4    4
#define NSEQ  4096
#define CDIM  1024
#define NH    16
#define HD    64
#define NBH   (B4*NH)
#define KVSPLIT 8

// device-global scratch (no runtime allocation)
static __device__ float g_x  [B4 * NSEQ * CDIM];   // tf32-rounded X
static __device__ float g_wk [CDIM * CDIM];        // tf32-rounded Wk
static __device__ float g_wv [CDIM * CDIM];        // tf32-rounded Wv
static __device__ float g_wo [CDIM * CDIM];        // tf32-rounded Wo
static __device__ float g_k  [NBH * NSEQ * HD];    // [B,H,N,D]
static __device__ float g_v  [NBH * NSEQ * HD];
static __device__ float g_kv [NBH * HD * HD];      // fp32, scaled
static __device__ float g_kvp[KVSPLIT * NBH * HD * HD];
static __device__ float g_r  [B4 * CDIM * CDIM];   // R[c][he], tf32-rounded
static __device__ float g_gt [B4 * CDIM * CDIM];   // Gt[co][c], tf32-rounded

__device__ __forceinline__ float tf32r(float x) {
    uint32_t u;
    asm("cvt.rna.tf32.f32 %0, %1;" : "=r"(u) : "f"(x));
    return __uint_as_float(u);
}
__device__ __forceinline__ uint32_t smem_u32(const void* p) {
    uint32_t a;
    asm("{ .reg .u64 t; cvta.to.shared.u64 t, %1; cvt.u32.u64 %0, t; }"
        : "=r"(a) : "l"(p));
    return a;
}
#define CP16(saddr, gptr) \
    asm volatile("cp.async.cg.shared.global [%0], [%1], 16;" :: "r"(saddr), "l"(gptr))
#define CP_COMMIT()  asm volatile("cp.async.commit_group;")
#define CP_WAIT1()   asm volatile("cp.async.wait_group 1;")
#define CP_WAIT0()   asm volatile("cp.async.wait_group 0;")

__device__ __forceinline__ void mma8(float c[4], const float a[4], const float b[2]) {
    const uint32_t* A  = reinterpret_cast<const uint32_t*>(a);
    const uint32_t* Bv = reinterpret_cast<const uint32_t*>(b);
    asm volatile(
        "mma.sync.aligned.m16n8k8.row.col.f32.tf32.tf32.f32 "
        "{%0,%1,%2,%3}, {%4,%5,%6,%7}, {%8,%9}, {%0,%1,%2,%3};\n"
        : "+f"(c[0]), "+f"(c[1]), "+f"(c[2]), "+f"(c[3])
        : "r"(A[0]), "r"(A[1]), "r"(A[2]), "r"(A[3]),
          "r"(Bv[0]), "r"(Bv[1]));
}

// ---------------------------------------------------------------------------
// prepass: tf32-round into device-global copies (R6-proven body)
// ---------------------------------------------------------------------------
__global__ __launch_bounds__(256, 1)
void round_tf32(const float* __restrict__ src, int which)
{
    float* dst = (which == 0) ? g_x
               : (which == 1) ? g_wk
               : (which == 2) ? g_wv : g_wo;
    const int i = blockIdx.x * 256 + threadIdx.x;
    float4 v = reinterpret_cast<const float4*>(src)[i];
    reinterpret_cast<float4*>(dst)[i] =
        make_float4(tf32r(v.x), tf32r(v.y), tf32r(v.z), tf32r(v.w));
}

// ---------------------------------------------------------------------------
// proj_kv: K/V projections (R6-proven proj2 MODE0 body; z selects Wk/Wv).
// C[m,n] = sum_k X[m,k]*W[n,k], scattered into g_k/g_v [B,H,N,D].
// grid (8, 128, 2), 256 threads, (256,2).
// ---------------------------------------------------------------------------
__global__ __launch_bounds__(256, 2)
void proj_kv()
{
    __shared__ float sA[2][128][20];
    __shared__ float sB[2][128][20];

    const int tid  = threadIdx.x;
    const int lane = tid & 31, warpId = tid >> 5;
    const int g  = lane >> 2, t = lane & 3;
    const int wm = warpId & 1, wn = warpId >> 1;
    const int n0 = blockIdx.x * 128;
    const int m0 = blockIdx.y * 128;
    const int z  = blockIdx.z;

    const float* A = (const float*)g_x;
    const float* W = (z == 0) ? (const float*)g_wk : (const float*)g_wv;

    const int lr  = tid >> 1;
    const int lco = (tid & 1) * 8;
    const float* gA = A + (size_t)(m0 + lr) * CDIM + lco;
    const float* gB = W + (size_t)(n0 + lr) * CDIM + lco;
    const uint32_t saA = smem_u32(&sA[0][lr][lco]);
    const uint32_t saB = smem_u32(&sB[0][lr][lco]);
    const uint32_t STG = 128 * 20 * 4;

    auto load_stage = [&](int s, int kt) {
        const float* pa = gA + kt * 16;
        const float* pb = gB + kt * 16;
        const uint32_t oa = saA + (uint32_t)s * STG;
        const uint32_t ob = saB + (uint32_t)s * STG;
        CP16(oa,      pa);
        CP16(oa + 16, pa + 4);
        CP16(ob,      pb);
        CP16(ob + 16, pb + 4);
        CP_COMMIT();
    };

    float acc[4][4][4];
#pragma unroll
    for (int a = 0; a < 4; ++a)
#pragma unroll
        for (int b = 0; b < 4; ++b)
#pragma unroll
            for (int c = 0; c < 4; ++c) acc[a][b][c] = 0.f;

    load_stage(0, 0);
    for (int kt = 0; kt < 64; ++kt) {
        const int cur = kt & 1;
        if (kt < 63) load_stage(cur ^ 1, kt + 1);
        if (kt < 63) CP_WAIT1(); else CP_WAIT0();
        __syncthreads();
#pragma unroll
        for (int ks = 0; ks < 2; ++ks) {
            const int kk = ks * 8;
            float af[4][4], bfr[4][2];
#pragma unroll
            for (int mi = 0; mi < 4; ++mi) {
                const int rm = wm * 64 + mi * 16 + g;
                af[mi][0] = sA[cur][rm][kk + t];
                af[mi][1] = sA[cur][rm + 8][kk + t];
                af[mi][2] = sA[cur][rm][kk + t + 4];
                af[mi][3] = sA[cur][rm + 8][kk + t + 4];
            }
#pragma unroll
            for (int ni = 0; ni < 4; ++ni) {
                const int cn = wn * 32 + ni * 8 + g;
                bfr[ni][0] = sB[cur][cn][kk + t];
                bfr[ni][1] = sB[cur][cn][kk + t + 4];
            }
#pragma unroll
            for (int mi = 0; mi < 4; ++mi)
#pragma unroll
                for (int ni = 0; ni < 4; ++ni)
                    mma8(acc[mi][ni], af[mi], bfr[ni]);
        }
        __syncthreads();
    }

    float* qkv = (z == 0) ? g_k : g_v;

#pragma unroll
    for (int mi = 0; mi < 4; ++mi) {
#pragma unroll
        for (int ni = 0; ni < 4; ++ni) {
            const int row = m0 + wm * 64 + mi * 16 + g;
            const int col = n0 + wn * 32 + ni * 8 + 2 * t;
            const int b = row >> 12, n = row & (NSEQ - 1);
            const int h = col >> 6,  d = col & (HD - 1);
            float* p = qkv + (((size_t)(b * NH + h) * NSEQ + n) * HD + d);
            *reinterpret_cast<float2*>(p) =
                make_float2(acc[mi][ni][0], acc[mi][ni][1]);
            *reinterpret_cast<float2*>(p + 8 * HD) =
                make_float2(acc[mi][ni][2], acc[mi][ni][3]);
        }
    }
}

// ---------------------------------------------------------------------------
// kv partial (R6-proven): kvp[split][bh] = sum_{n in split} k[n,d]*v[n,e]
// ---------------------------------------------------------------------------
__global__ __launch_bounds__(256, 1)
void kv_partial()
{
    __shared__ float sk[2][32][72];
    __shared__ float sv[2][32][72];
    const int bh = blockIdx.x;
    const int split = blockIdx.y;
    const int nt0 = split * 16;
    const float* Kp = g_k + (size_t)bh * NSEQ * HD;
    const float* Vp = g_v + (size_t)bh * NSEQ * HD;

    const int tid = threadIdx.x;
    const int lane = tid & 31, warpId = tid >> 5;
    const int g = lane >> 2, t = lane & 3;
    const int wm = warpId & 1, wn = warpId >> 1;
    const int lrow = tid >> 4;
    const int lc   = (tid & 15) * 4;

    float4 rk0, rk1, rv0, rv1;
    auto fetch = [&](int nt) {
        const size_t base = (size_t)(nt * 32 + lrow) * HD + lc;
        rk0 = *reinterpret_cast<const float4*>(Kp + base);
        rk1 = *reinterpret_cast<const float4*>(Kp + base + 16 * HD);
        rv0 = *reinterpret_cast<const float4*>(Vp + base);
        rv1 = *reinterpret_cast<const float4*>(Vp + base + 16 * HD);
    };
    auto cvt4 = [](float4 v) {
        return make_float4(tf32r(v.x), tf32r(v.y), tf32r(v.z), tf32r(v.w));
    };
    auto stage = [&](int bf) {
        *reinterpret_cast<float4*>(&sk[bf][lrow][lc])      = cvt4(rk0);
        *reinterpret_cast<float4*>(&sk[bf][lrow + 16][lc]) = cvt4(rk1);
        *reinterpret_cast<float4*>(&sv[bf][lrow][lc])      = cvt4(rv0);
        *reinterpret_cast<float4*>(&sv[bf][lrow + 16][lc]) = cvt4(rv1);
    };

    float acc[2][2][4];
#pragma unroll
    for (int a = 0; a < 2; ++a)
#pragma unroll
        for (int b = 0; b < 2; ++b)
#pragma unroll
            for (int c = 0; c < 4; ++c) acc[a][b][c] = 0.f;

    fetch(nt0); stage(0); __syncthreads();
    int buf = 0;
    for (int it = 0; it < 16; ++it) {
        if (it < 15) fetch(nt0 + it + 1);
#pragma unroll
        for (int ks = 0; ks < 4; ++ks) {
            const int kk = ks * 8;
            float af[2][4], bfr[2][2];
#pragma unroll
            for (int mi = 0; mi < 2; ++mi) {
                const int rd = wm * 32 + mi * 16 + g;
                af[mi][0] = sk[buf][kk + t][rd];
                af[mi][1] = sk[buf][kk + t][rd + 8];
                af[mi][2] = sk[buf][kk + t + 4][rd];
                af[mi][3] = sk[buf][kk + t + 4][rd + 8];
            }
#pragma unroll
            for (int ni = 0; ni < 2; ++ni) {
                const int ce = wn * 16 + ni * 8 + g;
                bfr[ni][0] = sv[buf][kk + t][ce];
                bfr[ni][1] = sv[buf][kk + t + 4][ce];
            }
#pragma unroll
            for (int mi = 0; mi < 2; ++mi)
#pragma unroll
                for (int ni = 0; ni < 2; ++ni)
                    mma8(acc[mi][ni], af[mi], bfr[ni]);
        }
        if (it < 15) { stage(buf ^ 1); __syncthreads(); buf ^= 1; }
    }

    float* O = g_kvp + ((size_t)split * NBH + bh) * HD * HD;
#pragma unroll
    for (int mi = 0; mi < 2; ++mi)
#pragma unroll
        for (int ni = 0; ni < 2; ++ni) {
            const int d0 = wm * 32 + mi * 16 + g;
            const int e  = wn * 16 + ni * 8 + 2 * t;
            *reinterpret_cast<float2*>(O + (size_t)d0 * HD + e) =
                make_float2(acc[mi][ni][0], acc[mi][ni][1]);
            *reinterpret_cast<float2*>(O + (size_t)(d0 + 8) * HD + e) =
                make_float2(acc[mi][ni][2], acc[mi][ni][3]);
        }
}

__global__ __launch_bounds__(256, 1)
void kv_reduce()
{
    const int i = blockIdx.x * 256 + threadIdx.x;   // float4 index
    float4 s = make_float4(0.f, 0.f, 0.f, 0.f);
#pragma unroll
    for (int sp = 0; sp < KVSPLIT; ++sp) {
        float4 v = *reinterpret_cast<const float4*>(g_kvp + (size_t)sp * NBH * HD * HD + i * 4);
        s.x += v.x; s.y += v.y; s.z += v.z; s.w += v.w;
    }
    *reinterpret_cast<float4*>(g_kv + (size_t)i * 4) =
        make_float4(s.x * 0.125f, s.y * 0.125f, s.z * 0.125f, s.w * 0.125f);
}

// ---------------------------------------------------------------------------
// r_build (scalar SIMT, spill-proof: one scalar accumulator, no arrays):
// R_b[c, h*64+e] = sum_d Wq[h*64+d, c] * kv_bh[d, e]  (Wq exact fp32)
// grid (256 c-chunks of 4, 16 h, 4 b), 256 threads: thread = (cl 0..3, e 0..63)
// ---------------------------------------------------------------------------
__global__ __launch_bounds__(256, 1)
void r_build(const float* __restrict__ Wq)
{
    __shared__ float skv[64][64];
    __shared__ float swq[4][64];
    const int b  = blockIdx.z, h = blockIdx.y;
    const int c0 = blockIdx.x * 4;
    const int tid = threadIdx.x;
    const int cl = tid >> 6;        // 0..3
    const int e  = tid & 63;        // 0..63

    const float* KV = g_kv + (size_t)(b * NH + h) * HD * HD;
    for (int i = tid; i < 4096; i += 256)
        skv[i >> 6][i & 63] = KV[i];
    // swq[cl][d] = Wq[(h*64+d)*CDIM + c0+cl]
    swq[cl][e] = Wq[(size_t)(h * 64 + e) * CDIM + c0 + cl];
    __syncthreads();

    float acc = 0.f;
    for (int d = 0; d < 64; ++d)
        acc += swq[cl][d] * skv[d][e];

    g_r[(size_t)b * CDIM * CDIM + (size_t)(c0 + cl) * CDIM + h * 64 + e] = tf32r(acc);
}

// ---------------------------------------------------------------------------
// gemm_b: R6-proven proj2 body, compile-time K=1024 and strides; per-b pointers
// via compile-time-selected globals (same ternary pattern R6 proved).
// MODE 0: Gt_b[co][c] = sum_he Wo[co,he]*R_b[c,he], tf32-rounded. grid (8,8,4)
// MODE 1: out_b[n][co] = sum_c X_b[n,c]*Gt_b[co,c] + bo[co].       grid (8,32,4)
// ---------------------------------------------------------------------------
template<int MODE>
__global__ __launch_bounds__(256, 2)
void gemm_b(const float* __restrict__ bias, float* __restrict__ outp)
{
    __shared__ float sA[2][128][20];
    __shared__ float sB[2][128][20];

    const int tid  = threadIdx.x;
    const int lane = tid & 31, warpId = tid >> 5;
    const int g  = lane >> 2, t = lane & 3;
    const int wm = warpId & 1, wn = warpId >> 1;
    const int n0 = blockIdx.x * 128;
    const int m0 = blockIdx.y * 128;
    const int z  = blockIdx.z;

    const size_t M1c = (size_t)CDIM * CDIM;
    const size_t MXc = (size_t)NSEQ * CDIM;

    const float* A = (MODE == 0) ? (const float*)g_wo
                                 : (const float*)g_x + (size_t)z * MXc;
    const float* B = (MODE == 0) ? (const float*)g_r  + (size_t)z * M1c
                                 : (const float*)g_gt + (size_t)z * M1c;
    float*       C = (MODE == 0) ? (float*)g_gt + (size_t)z * M1c
                                 : outp + (size_t)z * MXc;

    const int lr  = tid >> 1;
    const int lco = (tid & 1) * 8;
    const float* gA = A + (size_t)(m0 + lr) * CDIM + lco;
    const float* gB = B + (size_t)(n0 + lr) * CDIM + lco;
    const uint32_t saA = smem_u32(&sA[0][lr][lco]);
    const uint32_t saB = smem_u32(&sB[0][lr][lco]);
    const uint32_t STG = 128 * 20 * 4;

    auto load_stage = [&](int s, int kt) {
        const float* pa = gA + kt * 16;
        const float* pb = gB + kt * 16;
        const uint32_t oa = saA + (uint32_t)s * STG;
        const uint32_t ob = saB + (uint32_t)s * STG;
        CP16(oa,      pa);
        CP16(oa + 16, pa + 4);
        CP16(ob,      pb);
        CP16(ob + 16, pb + 4);
        CP_COMMIT();
    };

    float acc[4][4][4];
#pragma unroll
    for (int a = 0; a < 4; ++a)
#pragma unroll
        for (int b = 0; b < 4; ++b)
#pragma unroll
            for (int c = 0; c < 4; ++c) acc[a][b][c] = 0.f;

    load_stage(0, 0);
    for (int kt = 0; kt < 64; ++kt) {
        const int cur = kt & 1;
        if (kt < 63) load_stage(cur ^ 1, kt + 1);
        if (kt < 63) CP_WAIT1(); else CP_WAIT0();
        __syncthreads();
#pragma unroll
        for (int ks = 0; ks < 2; ++ks) {
            const int kk = ks * 8;
            float af[4][4], bfr[4][2];
#pragma unroll
            for (int mi = 0; mi < 4; ++mi) {
                const int rm = wm * 64 + mi * 16 + g;
                af[mi][0] = sA[cur][rm][kk + t];
                af[mi][1] = sA[cur][rm + 8][kk + t];
                af[mi][2] = sA[cur][rm][kk + t + 4];
                af[mi][3] = sA[cur][rm + 8][kk + t + 4];
            }
#pragma unroll
            for (int ni = 0; ni < 4; ++ni) {
                const int cn = wn * 32 + ni * 8 + g;
                bfr[ni][0] = sB[cur][cn][kk + t];
                bfr[ni][1] = sB[cur][cn][kk + t + 4];
            }
#pragma unroll
            for (int mi = 0; mi < 4; ++mi)
#pragma unroll
                for (int ni = 0; ni < 4; ++ni)
                    mma8(acc[mi][ni], af[mi], bfr[ni]);
        }
        __syncthreads();
    }

#pragma unroll
    for (int mi = 0; mi < 4; ++mi) {
#pragma unroll
        for (int ni = 0; ni < 4; ++ni) {
            const int row = m0 + wm * 64 + mi * 16 + g;
            const int col = n0 + wn * 32 + ni * 8 + 2 * t;
            float* p0 = C + (size_t)row * CDIM + col;
            float* p1 = C + (size_t)(row + 8) * CDIM + col;
            if (MODE == 0) {
                *reinterpret_cast<float2*>(p0) =
                    make_float2(tf32r(acc[mi][ni][0]), tf32r(acc[mi][ni][1]));
                *reinterpret_cast<float2*>(p1) =
                    make_float2(tf32r(acc[mi][ni][2]), tf32r(acc[mi][ni][3]));
            } else {
                const float b0v = bias[col], b1v = bias[col + 1];
                *reinterpret_cast<float2*>(p0) =
                    make_float2(acc[mi][ni][0] + b0v, acc[mi][ni][1] + b1v);
                *reinterpret_cast<float2*>(p1) =
                    make_float2(acc[mi][ni][2] + b0v, acc[mi][ni][3] + b1v);
            }
        }
    }
}

extern "C" void kernel_launch(void* const* d_in, const int* in_sizes, int n_in,
                              void* d_out, int out_size)
{
    (void)in_sizes; (void)n_in; (void)out_size;
    const float* x  = (const float*)d_in[0];
    const float* Wq = (const float*)d_in[1];
    const float* Wk = (const float*)d_in[2];
    const float* Wv = (const float*)d_in[3];
    const float* Wo = (const float*)d_in[4];
    const float* bo = (const float*)d_in[5];
    float* out = (float*)d_out;

    // prepass: tf32-round X, Wk, Wv, Wo (Wq stays exact fp32 for r_build)
    round_tf32<<<(B4 * NSEQ * CDIM / 4) / 256, 256>>>(x, 0);
    round_tf32<<<(CDIM * CDIM / 4) / 256, 256>>>(Wk, 1);
    round_tf32<<<(CDIM * CDIM / 4) / 256, 256>>>(Wv, 2);
    round_tf32<<<(CDIM * CDIM / 4) / 256, 256>>>(Wo, 3);

    // K and V projections (R6-proven body)
    proj_kv<<<dim3(CDIM / 128, (B4 * NSEQ) / 128, 2), 256>>>();

    // kv = 0.125 * k^T v per (b,h)  (R6-proven split-8 + reduce)
    kv_partial<<<dim3(NBH, KVSPLIT), 256>>>();
    kv_reduce<<<(NBH * HD * HD / 4) / 256, 256>>>();

    // R_b[c,he] = sum_d Wq[hd,c]*kv[d,e]  (exact fp32, rounded store)
    r_build<<<dim3(256, NH, B4), 256>>>(Wq);

    // Gt_b = Wo (contract he) R_b^T ; then out = X Gt^T + bo
    gemm_b<0><<<dim3(8, 8, B4), 256>>>(nullptr, nullptr);
    gemm_b<1><<<dim3(8, 32, B4), 256>>>(bo, out);
}

// round 16
// speedup vs baseline: 1.0568x; 1.0554x over previous
#include <cuda_runtime.h>
#include <cstdint>
#include <cstddef>

#define B4    4
#define NSEQ  4096
#define CDIM  1024
#define NH    16
#define HD    64
#define NBH   (B4*NH)

// device-global scratch (no runtime allocation)
static __device__ float g_x  [B4 * NSEQ * CDIM];   // tf32-rounded X       64MB
static __device__ float g_xt [B4 * NSEQ * CDIM];   // XT[c][n] per b       64MB
static __device__ float g_wk [CDIM * CDIM];        // tf32-rounded Wk
static __device__ float g_wv [CDIM * CDIM];        // tf32-rounded Wv
static __device__ float g_wo [CDIM * CDIM];        // tf32-rounded Wo
static __device__ float g_s  [B4 * CDIM * CDIM];   // S = X^T X (raw upper -> rounded full)
static __device__ float g_p  [B4 * CDIM * CDIM];   // P = Wk @ S (rounded)
static __device__ float g_f  [B4 * CDIM * CDIM];   // F = P @ Wv^T (raw fp32)
static __device__ float g_r  [B4 * CDIM * CDIM];   // R[c][he] (rounded)
static __device__ float g_gt [B4 * CDIM * CDIM];   // Gt[co][c] (rounded)

__device__ __forceinline__ float tf32r(float x) {
    uint32_t u;
    asm("cvt.rna.tf32.f32 %0, %1;" : "=r"(u) : "f"(x));
    return __uint_as_float(u);
}
__device__ __forceinline__ uint32_t smem_u32(const void* p) {
    uint32_t a;
    asm("{ .reg .u64 t; cvta.to.shared.u64 t, %1; cvt.u32.u64 %0, t; }"
        : "=r"(a) : "l"(p));
    return a;
}
#define CP16(saddr, gptr) \
    asm volatile("cp.async.cg.shared.global [%0], [%1], 16;" :: "r"(saddr), "l"(gptr))
#define CP_COMMIT()  asm volatile("cp.async.commit_group;")
#define CP_WAIT1()   asm volatile("cp.async.wait_group 1;")
#define CP_WAIT0()   asm volatile("cp.async.wait_group 0;")

__device__ __forceinline__ void mma8(float c[4], const float a[4], const float b[2]) {
    const uint32_t* A  = reinterpret_cast<const uint32_t*>(a);
    const uint32_t* Bv = reinterpret_cast<const uint32_t*>(b);
    asm volatile(
        "mma.sync.aligned.m16n8k8.row.col.f32.tf32.tf32.f32 "
        "{%0,%1,%2,%3}, {%4,%5,%6,%7}, {%8,%9}, {%0,%1,%2,%3};\n"
        : "+f"(c[0]), "+f"(c[1]), "+f"(c[2]), "+f"(c[3])
        : "r"(A[0]), "r"(A[1]), "r"(A[2]), "r"(A[3]),
          "r"(Bv[0]), "r"(Bv[1]));
}

// ---------------------------------------------------------------------------
// prepass: tf32-round into device-global copies (proven body)
// ---------------------------------------------------------------------------
__global__ __launch_bounds__(256, 1)
void round_tf32(const float* __restrict__ src, int which)
{
    float* dst = (which == 0) ? g_x
               : (which == 1) ? g_wk
               : (which == 2) ? g_wv : g_wo;
    const int i = blockIdx.x * 256 + threadIdx.x;
    float4 v = reinterpret_cast<const float4*>(src)[i];
    reinterpret_cast<float4*>(dst)[i] =
        make_float4(tf32r(v.x), tf32r(v.y), tf32r(v.z), tf32r(v.w));
}

// ---------------------------------------------------------------------------
// transpose: XT_b[c][n] = X_b[n][c].  32x32 tiles, smem 32x33. grid (32,128,4)
// ---------------------------------------------------------------------------
__global__ __launch_bounds__(256, 1)
void transp()
{
    __shared__ float t[32][33];
    const int b  = blockIdx.z;
    const int c0 = blockIdx.x * 32;
    const int n0 = blockIdx.y * 32;
    const int tx = threadIdx.x & 31;
    const int ty = threadIdx.x >> 5;          // 0..7

    const float* X = g_x + (size_t)b * NSEQ * CDIM;
#pragma unroll
    for (int i = 0; i < 4; ++i)
        t[ty + i * 8][tx] = X[(size_t)(n0 + ty + i * 8) * CDIM + c0 + tx];
    __syncthreads();

    float* XT = g_xt + (size_t)b * NSEQ * CDIM;
#pragma unroll
    for (int i = 0; i < 4; ++i)
        XT[(size_t)(c0 + ty + i * 8) * NSEQ + n0 + tx] = t[tx][ty + i * 8];
}

// ---------------------------------------------------------------------------
// sgemm_tri: S upper tiles = XT @ XT^T, K=4096 (COMPILE-TIME), lda=ldb=NSEQ.
// Byte-level clone of the PROVEN gemm_b body; triangle by early-exit on a full
// 8x8 grid (no LUT, no runtime params). Raw fp32 store. grid (8,8,4).
// ---------------------------------------------------------------------------
__global__ __launch_bounds__(256, 2)
void sgemm_tri()
{
    __shared__ float sA[2][128][20];
    __shared__ float sB[2][128][20];

    if (blockIdx.y > blockIdx.x) return;   // upper triangle only (mt <= nt)

    const int tid  = threadIdx.x;
    const int lane = tid & 31, warpId = tid >> 5;
    const int g  = lane >> 2, t = lane & 3;
    const int wm = warpId & 1, wn = warpId >> 1;
    const int n0 = blockIdx.x * 128;
    const int m0 = blockIdx.y * 128;
    const int z  = blockIdx.z;

    const size_t MXc = (size_t)NSEQ * CDIM;
    const float* A = (const float*)g_xt + (size_t)z * MXc;
    float*       C = g_s + (size_t)z * CDIM * CDIM;

    const int lr  = tid >> 1;
    const int lco = (tid & 1) * 8;
    const float* gA = A + (size_t)(m0 + lr) * NSEQ + lco;
    const float* gB = A + (size_t)(n0 + lr) * NSEQ + lco;
    const uint32_t saA = smem_u32(&sA[0][lr][lco]);
    const uint32_t saB = smem_u32(&sB[0][lr][lco]);
    const uint32_t STG = 128 * 20 * 4;

    auto load_stage = [&](int s, int kt) {
        const float* pa = gA + kt * 16;
        const float* pb = gB + kt * 16;
        const uint32_t oa = saA + (uint32_t)s * STG;
        const uint32_t ob = saB + (uint32_t)s * STG;
        CP16(oa,      pa);
        CP16(oa + 16, pa + 4);
        CP16(ob,      pb);
        CP16(ob + 16, pb + 4);
        CP_COMMIT();
    };

    float acc[4][4][4];
#pragma unroll
    for (int a = 0; a < 4; ++a)
#pragma unroll
        for (int b = 0; b < 4; ++b)
#pragma unroll
            for (int c = 0; c < 4; ++c) acc[a][b][c] = 0.f;

    load_stage(0, 0);
    for (int kt = 0; kt < 256; ++kt) {
        const int cur = kt & 1;
        if (kt < 255) load_stage(cur ^ 1, kt + 1);
        if (kt < 255) CP_WAIT1(); else CP_WAIT0();
        __syncthreads();
#pragma unroll
        for (int ks = 0; ks < 2; ++ks) {
            const int kk = ks * 8;
            float af[4][4], bfr[4][2];
#pragma unroll
            for (int mi = 0; mi < 4; ++mi) {
                const int rm = wm * 64 + mi * 16 + g;
                af[mi][0] = sA[cur][rm][kk + t];
                af[mi][1] = sA[cur][rm + 8][kk + t];
                af[mi][2] = sA[cur][rm][kk + t + 4];
                af[mi][3] = sA[cur][rm + 8][kk + t + 4];
            }
#pragma unroll
            for (int ni = 0; ni < 4; ++ni) {
                const int cn = wn * 32 + ni * 8 + g;
                bfr[ni][0] = sB[cur][cn][kk + t];
                bfr[ni][1] = sB[cur][cn][kk + t + 4];
            }
#pragma unroll
            for (int mi = 0; mi < 4; ++mi)
#pragma unroll
                for (int ni = 0; ni < 4; ++ni)
                    mma8(acc[mi][ni], af[mi], bfr[ni]);
        }
        __syncthreads();
    }

#pragma unroll
    for (int mi = 0; mi < 4; ++mi) {
#pragma unroll
        for (int ni = 0; ni < 4; ++ni) {
            const int row = m0 + wm * 64 + mi * 16 + g;
            const int col = n0 + wn * 32 + ni * 8 + 2 * t;
            *reinterpret_cast<float2*>(C + (size_t)row * CDIM + col) =
                make_float2(acc[mi][ni][0], acc[mi][ni][1]);
            *reinterpret_cast<float2*>(C + (size_t)(row + 8) * CDIM + col) =
                make_float2(acc[mi][ni][2], acc[mi][ni][3]);
        }
    }
}

// ---------------------------------------------------------------------------
// s_mirror (IN PLACE, pure scalar — one float per thread, zero arrays):
// fill lower triangle from upper, tf32-round everything. Race-safe because
// tf32r is idempotent. grid (16384, 4), 256 threads.
// ---------------------------------------------------------------------------
__global__ __launch_bounds__(256, 1)
void s_mirror()
{
    const int b  = blockIdx.y;
    const int i  = blockIdx.x * 256 + threadIdx.x;   // element index in [0, 1M)
    const int c1 = i >> 10;
    const int c2 = i & (CDIM - 1);
    float* U = g_s + (size_t)b * CDIM * CDIM;
    float v;
    if ((c1 >> 7) <= (c2 >> 7)) v = U[(size_t)c1 * CDIM + c2];
    else                        v = U[(size_t)c2 * CDIM + c1];
    U[(size_t)c1 * CDIM + c2] = tf32r(v);
}

// ---------------------------------------------------------------------------
// gemm_b: PROVEN body, K=1024 compile-time, operands selected per MODE.
// MODE 0: Gt_b = Wo (contract he) R_b^T, rounded.            grid (8,8,4)
// MODE 1: out_b = X_b @ Gt_b^T + bias.                       grid (8,32,4)
// MODE 2: P_b = Wk @ S_b (S symmetric), rounded.             grid (8,8,4)
// MODE 3: F_b = P_b @ Wv^T, raw fp32.                        grid (8,8,4)
// ---------------------------------------------------------------------------
template<int MODE>
__global__ __launch_bounds__(256, 2)
void gemm_b(const float* __restrict__ bias, float* __restrict__ outp)
{
    __shared__ float sA[2][128][20];
    __shared__ float sB[2][128][20];

    const int tid  = threadIdx.x;
    const int lane = tid & 31, warpId = tid >> 5;
    const int g  = lane >> 2, t = lane & 3;
    const int wm = warpId & 1, wn = warpId >> 1;
    const int n0 = blockIdx.x * 128;
    const int m0 = blockIdx.y * 128;
    const int z  = blockIdx.z;

    const size_t M1c = (size_t)CDIM * CDIM;
    const size_t MXc = (size_t)NSEQ * CDIM;

    const float* A = (MODE == 0) ? (const float*)g_wo
                   : (MODE == 1) ? (const float*)g_x + (size_t)z * MXc
                   : (MODE == 2) ? (const float*)g_wk
                   :               (const float*)g_p + (size_t)z * M1c;
    const float* B = (MODE == 0) ? (const float*)g_r  + (size_t)z * M1c
                   : (MODE == 1) ? (const float*)g_gt + (size_t)z * M1c
                   : (MODE == 2) ? (const float*)g_s  + (size_t)z * M1c
                   :               (const float*)g_wv;
    float*       C = (MODE == 0) ? (float*)g_gt + (size_t)z * M1c
                   : (MODE == 1) ? outp + (size_t)z * MXc
                   : (MODE == 2) ? (float*)g_p + (size_t)z * M1c
                   :               (float*)g_f + (size_t)z * M1c;

    const int lr  = tid >> 1;
    const int lco = (tid & 1) * 8;
    const float* gA = A + (size_t)(m0 + lr) * CDIM + lco;
    const float* gB = B + (size_t)(n0 + lr) * CDIM + lco;
    const uint32_t saA = smem_u32(&sA[0][lr][lco]);
    const uint32_t saB = smem_u32(&sB[0][lr][lco]);
    const uint32_t STG = 128 * 20 * 4;

    auto load_stage = [&](int s, int kt) {
        const float* pa = gA + kt * 16;
        const float* pb = gB + kt * 16;
        const uint32_t oa = saA + (uint32_t)s * STG;
        const uint32_t ob = saB + (uint32_t)s * STG;
        CP16(oa,      pa);
        CP16(oa + 16, pa + 4);
        CP16(ob,      pb);
        CP16(ob + 16, pb + 4);
        CP_COMMIT();
    };

    float acc[4][4][4];
#pragma unroll
    for (int a = 0; a < 4; ++a)
#pragma unroll
        for (int b = 0; b < 4; ++b)
#pragma unroll
            for (int c = 0; c < 4; ++c) acc[a][b][c] = 0.f;

    load_stage(0, 0);
    for (int kt = 0; kt < 64; ++kt) {
        const int cur = kt & 1;
        if (kt < 63) load_stage(cur ^ 1, kt + 1);
        if (kt < 63) CP_WAIT1(); else CP_WAIT0();
        __syncthreads();
#pragma unroll
        for (int ks = 0; ks < 2; ++ks) {
            const int kk = ks * 8;
            float af[4][4], bfr[4][2];
#pragma unroll
            for (int mi = 0; mi < 4; ++mi) {
                const int rm = wm * 64 + mi * 16 + g;
                af[mi][0] = sA[cur][rm][kk + t];
                af[mi][1] = sA[cur][rm + 8][kk + t];
                af[mi][2] = sA[cur][rm][kk + t + 4];
                af[mi][3] = sA[cur][rm + 8][kk + t + 4];
            }
#pragma unroll
            for (int ni = 0; ni < 4; ++ni) {
                const int cn = wn * 32 + ni * 8 + g;
                bfr[ni][0] = sB[cur][cn][kk + t];
                bfr[ni][1] = sB[cur][cn][kk + t + 4];
            }
#pragma unroll
            for (int mi = 0; mi < 4; ++mi)
#pragma unroll
                for (int ni = 0; ni < 4; ++ni)
                    mma8(acc[mi][ni], af[mi], bfr[ni]);
        }
        __syncthreads();
    }

#pragma unroll
    for (int mi = 0; mi < 4; ++mi) {
#pragma unroll
        for (int ni = 0; ni < 4; ++ni) {
            const int row = m0 + wm * 64 + mi * 16 + g;
            const int col = n0 + wn * 32 + ni * 8 + 2 * t;
            float* p0 = C + (size_t)row * CDIM + col;
            float* p1 = C + (size_t)(row + 8) * CDIM + col;
            if (MODE == 1) {
                const float b0v = bias[col], b1v = bias[col + 1];
                *reinterpret_cast<float2*>(p0) =
                    make_float2(acc[mi][ni][0] + b0v, acc[mi][ni][1] + b1v);
                *reinterpret_cast<float2*>(p1) =
                    make_float2(acc[mi][ni][2] + b0v, acc[mi][ni][3] + b1v);
            } else if (MODE == 3) {
                *reinterpret_cast<float2*>(p0) =
                    make_float2(acc[mi][ni][0], acc[mi][ni][1]);
                *reinterpret_cast<float2*>(p1) =
                    make_float2(acc[mi][ni][2], acc[mi][ni][3]);
            } else {
                *reinterpret_cast<float2*>(p0) =
                    make_float2(tf32r(acc[mi][ni][0]), tf32r(acc[mi][ni][1]));
                *reinterpret_cast<float2*>(p1) =
                    make_float2(tf32r(acc[mi][ni][2]), tf32r(acc[mi][ni][3]));
            }
        }
    }
}

// ---------------------------------------------------------------------------
// r_build (scalar SIMT, spill-proof; R15-proven structure):
// R_b[c, h*64+e] = sum_d Wq[h*64+d, c] * 0.125*F_b[h*64+d, h*64+e]
// Wq exact fp32. grid (256 c-chunks of 4, 16 h, 4 b), 256 threads.
// ---------------------------------------------------------------------------
__global__ __launch_bounds__(256, 1)
void r_build(const float* __restrict__ Wq)
{
    __shared__ float skv[64][64];
    __shared__ float swq[4][64];
    const int b  = blockIdx.z, h = blockIdx.y;
    const int c0 = blockIdx.x * 4;
    const int tid = threadIdx.x;
    const int cl = tid >> 6;        // 0..3
    const int e  = tid & 63;        // 0..63

    const float* F = g_f + (size_t)b * CDIM * CDIM;
    for (int i = tid; i < 4096; i += 256) {
        const int d = i >> 6, ee = i & 63;
        skv[d][ee] = 0.125f * F[(size_t)(h * 64 + d) * CDIM + h * 64 + ee];
    }
    swq[cl][e] = Wq[(size_t)(h * 64 + e) * CDIM + c0 + cl];
    __syncthreads();

    float acc = 0.f;
    for (int d = 0; d < 64; ++d)
        acc += swq[cl][d] * skv[d][e];

    g_r[(size_t)b * CDIM * CDIM + (size_t)(c0 + cl) * CDIM + h * 64 + e] = tf32r(acc);
}

extern "C" void kernel_launch(void* const* d_in, const int* in_sizes, int n_in,
                              void* d_out, int out_size)
{
    (void)in_sizes; (void)n_in; (void)out_size;
    const float* x  = (const float*)d_in[0];
    const float* Wq = (const float*)d_in[1];
    const float* Wk = (const float*)d_in[2];
    const float* Wv = (const float*)d_in[3];
    const float* Wo = (const float*)d_in[4];
    const float* bo = (const float*)d_in[5];
    float* out = (float*)d_out;

    // prepass: tf32-round X, Wk, Wv, Wo (Wq stays exact fp32 for r_build)
    round_tf32<<<(B4 * NSEQ * CDIM / 4) / 256, 256>>>(x, 0);
    round_tf32<<<(CDIM * CDIM / 4) / 256, 256>>>(Wk, 1);
    round_tf32<<<(CDIM * CDIM / 4) / 256, 256>>>(Wv, 2);
    round_tf32<<<(CDIM * CDIM / 4) / 256, 256>>>(Wo, 3);

    // XT = X^T per batch
    transp<<<dim3(CDIM / 32, NSEQ / 32, B4), 256>>>();

    // S upper tiles = XT @ XT^T (K=4096), raw; mirror + round in place
    sgemm_tri<<<dim3(8, 8, B4), 256>>>();
    s_mirror<<<dim3(CDIM * CDIM / 256, B4), 256>>>();

    // P = Wk @ S ; F = P @ Wv^T (full; diagonal blocks are the kv matrices)
    gemm_b<2><<<dim3(8, 8, B4), 256>>>(nullptr, nullptr);
    gemm_b<3><<<dim3(8, 8, B4), 256>>>(nullptr, nullptr);

    // R_b[c,he] = sum_d Wq[hd,c] * 0.125*F[hd, he]  (exact fp32 Wq)
    r_build<<<dim3(256, NH, B4), 256>>>(Wq);

    // Gt_b = Wo (contract he) R_b^T ; out = X @ Gt^T + bo
    gemm_b<0><<<dim3(8, 8, B4), 256>>>(nullptr, nullptr);
    gemm_b<1><<<dim3(8, 32, B4), 256>>>(bo, out);
}

// round 17
// speedup vs baseline: 1.0572x; 1.0004x over previous
#include <cuda_runtime.h>
#include <cstdint>
#include <cstddef>

#define B4    4
#define NSEQ  4096
#define CDIM  1024
#define NH    16
#define HD    64
#define NBH   (B4*NH)

// device-global scratch (no runtime allocation)
static __device__ float g_x  [B4 * NSEQ * CDIM];   // tf32-rounded X       64MB
static __device__ float g_xt [B4 * NSEQ * CDIM];   // XT[c][n] per b       64MB
static __device__ float g_wk [CDIM * CDIM];        // tf32-rounded Wk
static __device__ float g_wv [CDIM * CDIM];        // tf32-rounded Wv
static __device__ float g_wo [CDIM * CDIM];        // tf32-rounded Wo
static __device__ float g_s  [B4 * CDIM * CDIM];   // S = X^T X (raw upper -> rounded full)
static __device__ float g_p  [B4 * CDIM * CDIM];   // P = Wk @ S (rounded)
static __device__ float g_f  [B4 * CDIM * CDIM];   // F = P @ Wv^T (raw fp32)
static __device__ float g_r  [B4 * CDIM * CDIM];   // R[c][he] (rounded)
static __device__ float g_gt [B4 * CDIM * CDIM];   // Gt[co][c] (rounded)

__device__ __forceinline__ float tf32r(float x) {
    uint32_t u;
    asm("cvt.rna.tf32.f32 %0, %1;" : "=r"(u) : "f"(x));
    return __uint_as_float(u);
}
__device__ __forceinline__ uint32_t smem_u32(const void* p) {
    uint32_t a;
    asm("{ .reg .u64 t; cvta.to.shared.u64 t, %1; cvt.u32.u64 %0, t; }"
        : "=r"(a) : "l"(p));
    return a;
}
#define CP16(saddr, gptr) \
    asm volatile("cp.async.cg.shared.global [%0], [%1], 16;" :: "r"(saddr), "l"(gptr))
#define CP_COMMIT()  asm volatile("cp.async.commit_group;")
#define CP_WAIT1()   asm volatile("cp.async.wait_group 1;")
#define CP_WAIT0()   asm volatile("cp.async.wait_group 0;")

__device__ __forceinline__ void mma8(float c[4], const float a[4], const float b[2]) {
    const uint32_t* A  = reinterpret_cast<const uint32_t*>(a);
    const uint32_t* Bv = reinterpret_cast<const uint32_t*>(b);
    asm volatile(
        "mma.sync.aligned.m16n8k8.row.col.f32.tf32.tf32.f32 "
        "{%0,%1,%2,%3}, {%4,%5,%6,%7}, {%8,%9}, {%0,%1,%2,%3};\n"
        : "+f"(c[0]), "+f"(c[1]), "+f"(c[2]), "+f"(c[3])
        : "r"(A[0]), "r"(A[1]), "r"(A[2]), "r"(A[3]),
          "r"(Bv[0]), "r"(Bv[1]));
}

// ---------------------------------------------------------------------------
// prepass: tf32-round into device-global copies (proven body)
// ---------------------------------------------------------------------------
__global__ __launch_bounds__(256, 1)
void round_tf32(const float* __restrict__ src, int which)
{
    float* dst = (which == 0) ? g_x
               : (which == 1) ? g_wk
               : (which == 2) ? g_wv : g_wo;
    const int i = blockIdx.x * 256 + threadIdx.x;
    float4 v = reinterpret_cast<const float4*>(src)[i];
    reinterpret_cast<float4*>(dst)[i] =
        make_float4(tf32r(v.x), tf32r(v.y), tf32r(v.z), tf32r(v.w));
}

// ---------------------------------------------------------------------------
// transpose: XT_b[c][n] = X_b[n][c].  32x32 tiles, smem 32x33. grid (32,128,4)
// ---------------------------------------------------------------------------
__global__ __launch_bounds__(256, 1)
void transp()
{
    __shared__ float t[32][33];
    const int b  = blockIdx.z;
    const int c0 = blockIdx.x * 32;
    const int n0 = blockIdx.y * 32;
    const int tx = threadIdx.x & 31;
    const int ty = threadIdx.x >> 5;          // 0..7

    const float* X = g_x + (size_t)b * NSEQ * CDIM;
#pragma unroll
    for (int i = 0; i < 4; ++i)
        t[ty + i * 8][tx] = X[(size_t)(n0 + ty + i * 8) * CDIM + c0 + tx];
    __syncthreads();

    float* XT = g_xt + (size_t)b * NSEQ * CDIM;
#pragma unroll
    for (int i = 0; i < 4; ++i)
        XT[(size_t)(c0 + ty + i * 8) * NSEQ + n0 + tx] = t[tx][ty + i * 8];
}

// ---------------------------------------------------------------------------
// sgemm_tri: S upper tiles = XT @ XT^T, K=4096 (COMPILE-TIME), lda=ldb=NSEQ.
// Byte-level clone of the PROVEN gemm_b body; triangle by early-exit on a full
// 8x8 grid (no LUT, no runtime params). Raw fp32 store. grid (8,8,4).
// ---------------------------------------------------------------------------
__global__ __launch_bounds__(256, 2)
void sgemm_tri()
{
    __shared__ float sA[2][128][20];
    __shared__ float sB[2][128][20];

    if (blockIdx.y > blockIdx.x) return;   // upper triangle only (mt <= nt)

    const int tid  = threadIdx.x;
    const int lane = tid & 31, warpId = tid >> 5;
    const int g  = lane >> 2, t = lane & 3;
    const int wm = warpId & 1, wn = warpId >> 1;
    const int n0 = blockIdx.x * 128;
    const int m0 = blockIdx.y * 128;
    const int z  = blockIdx.z;

    const size_t MXc = (size_t)NSEQ * CDIM;
    const float* A = (const float*)g_xt + (size_t)z * MXc;
    float*       C = g_s + (size_t)z * CDIM * CDIM;

    const int lr  = tid >> 1;
    const int lco = (tid & 1) * 8;
    const float* gA = A + (size_t)(m0 + lr) * NSEQ + lco;
    const float* gB = A + (size_t)(n0 + lr) * NSEQ + lco;
    const uint32_t saA = smem_u32(&sA[0][lr][lco]);
    const uint32_t saB = smem_u32(&sB[0][lr][lco]);
    const uint32_t STG = 128 * 20 * 4;

    auto load_stage = [&](int s, int kt) {
        const float* pa = gA + kt * 16;
        const float* pb = gB + kt * 16;
        const uint32_t oa = saA + (uint32_t)s * STG;
        const uint32_t ob = saB + (uint32_t)s * STG;
        CP16(oa,      pa);
        CP16(oa + 16, pa + 4);
        CP16(ob,      pb);
        CP16(ob + 16, pb + 4);
        CP_COMMIT();
    };

    float acc[4][4][4];
#pragma unroll
    for (int a = 0; a < 4; ++a)
#pragma unroll
        for (int b = 0; b < 4; ++b)
#pragma unroll
            for (int c = 0; c < 4; ++c) acc[a][b][c] = 0.f;

    load_stage(0, 0);
    for (int kt = 0; kt < 256; ++kt) {
        const int cur = kt & 1;
        if (kt < 255) load_stage(cur ^ 1, kt + 1);
        if (kt < 255) CP_WAIT1(); else CP_WAIT0();
        __syncthreads();
#pragma unroll
        for (int ks = 0; ks < 2; ++ks) {
            const int kk = ks * 8;
            float af[4][4], bfr[4][2];
#pragma unroll
            for (int mi = 0; mi < 4; ++mi) {
                const int rm = wm * 64 + mi * 16 + g;
                af[mi][0] = sA[cur][rm][kk + t];
                af[mi][1] = sA[cur][rm + 8][kk + t];
                af[mi][2] = sA[cur][rm][kk + t + 4];
                af[mi][3] = sA[cur][rm + 8][kk + t + 4];
            }
#pragma unroll
            for (int ni = 0; ni < 4; ++ni) {
                const int cn = wn * 32 + ni * 8 + g;
                bfr[ni][0] = sB[cur][cn][kk + t];
                bfr[ni][1] = sB[cur][cn][kk + t + 4];
            }
#pragma unroll
            for (int mi = 0; mi < 4; ++mi)
#pragma unroll
                for (int ni = 0; ni < 4; ++ni)
                    mma8(acc[mi][ni], af[mi], bfr[ni]);
        }
        __syncthreads();
    }

#pragma unroll
    for (int mi = 0; mi < 4; ++mi) {
#pragma unroll
        for (int ni = 0; ni < 4; ++ni) {
            const int row = m0 + wm * 64 + mi * 16 + g;
            const int col = n0 + wn * 32 + ni * 8 + 2 * t;
            *reinterpret_cast<float2*>(C + (size_t)row * CDIM + col) =
                make_float2(acc[mi][ni][0], acc[mi][ni][1]);
            *reinterpret_cast<float2*>(C + (size_t)(row + 8) * CDIM + col) =
                make_float2(acc[mi][ni][2], acc[mi][ni][3]);
        }
    }
}

// ---------------------------------------------------------------------------
// s_mirror (IN PLACE, pure scalar — one float per thread, zero arrays):
// fill lower triangle from upper, tf32-round everything. Race-safe because
// tf32r is idempotent. grid (16384, 4), 256 threads.
// ---------------------------------------------------------------------------
__global__ __launch_bounds__(256, 1)
void s_mirror()
{
    const int b  = blockIdx.y;
    const int i  = blockIdx.x * 256 + threadIdx.x;   // element index in [0, 1M)
    const int c1 = i >> 10;
    const int c2 = i & (CDIM - 1);
    float* U = g_s + (size_t)b * CDIM * CDIM;
    float v;
    if ((c1 >> 7) <= (c2 >> 7)) v = U[(size_t)c1 * CDIM + c2];
    else                        v = U[(size_t)c2 * CDIM + c1];
    U[(size_t)c1 * CDIM + c2] = tf32r(v);
}

// ---------------------------------------------------------------------------
// gemm_b: PROVEN body, K=1024 compile-time, operands selected per MODE.
// MODE 0: Gt_b = Wo (contract he) R_b^T, rounded.            grid (8,8,4)
// MODE 1: out_b = X_b @ Gt_b^T + bias.                       grid (8,32,4)
// MODE 2: P_b = Wk @ S_b (S symmetric), rounded.             grid (8,8,4)
// MODE 3: F_b = P_b @ Wv^T, raw fp32.                        grid (8,8,4)
// ---------------------------------------------------------------------------
template<int MODE>
__global__ __launch_bounds__(256, 2)
void gemm_b(const float* __restrict__ bias, float* __restrict__ outp)
{
    __shared__ float sA[2][128][20];
    __shared__ float sB[2][128][20];

    const int tid  = threadIdx.x;
    const int lane = tid & 31, warpId = tid >> 5;
    const int g  = lane >> 2, t = lane & 3;
    const int wm = warpId & 1, wn = warpId >> 1;
    const int n0 = blockIdx.x * 128;
    const int m0 = blockIdx.y * 128;
    const int z  = blockIdx.z;

    const size_t M1c = (size_t)CDIM * CDIM;
    const size_t MXc = (size_t)NSEQ * CDIM;

    const float* A = (MODE == 0) ? (const float*)g_wo
                   : (MODE == 1) ? (const float*)g_x + (size_t)z * MXc
                   : (MODE == 2) ? (const float*)g_wk
                   :               (const float*)g_p + (size_t)z * M1c;
    const float* B = (MODE == 0) ? (const float*)g_r  + (size_t)z * M1c
                   : (MODE == 1) ? (const float*)g_gt + (size_t)z * M1c
                   : (MODE == 2) ? (const float*)g_s  + (size_t)z * M1c
                   :               (const float*)g_wv;
    float*       C = (MODE == 0) ? (float*)g_gt + (size_t)z * M1c
                   : (MODE == 1) ? outp + (size_t)z * MXc
                   : (MODE == 2) ? (float*)g_p + (size_t)z * M1c
                   :               (float*)g_f + (size_t)z * M1c;

    const int lr  = tid >> 1;
    const int lco = (tid & 1) * 8;
    const float* gA = A + (size_t)(m0 + lr) * CDIM + lco;
    const float* gB = B + (size_t)(n0 + lr) * CDIM + lco;
    const uint32_t saA = smem_u32(&sA[0][lr][lco]);
    const uint32_t saB = smem_u32(&sB[0][lr][lco]);
    const uint32_t STG = 128 * 20 * 4;

    auto load_stage = [&](int s, int kt) {
        const float* pa = gA + kt * 16;
        const float* pb = gB + kt * 16;
        const uint32_t oa = saA + (uint32_t)s * STG;
        const uint32_t ob = saB + (uint32_t)s * STG;
        CP16(oa,      pa);
        CP16(oa + 16, pa + 4);
        CP16(ob,      pb);
        CP16(ob + 16, pb + 4);
        CP_COMMIT();
    };

    float acc[4][4][4];
#pragma unroll
    for (int a = 0; a < 4; ++a)
#pragma unroll
        for (int b = 0; b < 4; ++b)
#pragma unroll
            for (int c = 0; c < 4; ++c) acc[a][b][c] = 0.f;

    load_stage(0, 0);
    for (int kt = 0; kt < 64; ++kt) {
        const int cur = kt & 1;
        if (kt < 63) load_stage(cur ^ 1, kt + 1);
        if (kt < 63) CP_WAIT1(); else CP_WAIT0();
        __syncthreads();
#pragma unroll
        for (int ks = 0; ks < 2; ++ks) {
            const int kk = ks * 8;
            float af[4][4], bfr[4][2];
#pragma unroll
            for (int mi = 0; mi < 4; ++mi) {
                const int rm = wm * 64 + mi * 16 + g;
                af[mi][0] = sA[cur][rm][kk + t];
                af[mi][1] = sA[cur][rm + 8][kk + t];
                af[mi][2] = sA[cur][rm][kk + t + 4];
                af[mi][3] = sA[cur][rm + 8][kk + t + 4];
            }
#pragma unroll
            for (int ni = 0; ni < 4; ++ni) {
                const int cn = wn * 32 + ni * 8 + g;
                bfr[ni][0] = sB[cur][cn][kk + t];
                bfr[ni][1] = sB[cur][cn][kk + t + 4];
            }
#pragma unroll
            for (int mi = 0; mi < 4; ++mi)
#pragma unroll
                for (int ni = 0; ni < 4; ++ni)
                    mma8(acc[mi][ni], af[mi], bfr[ni]);
        }
        __syncthreads();
    }

#pragma unroll
    for (int mi = 0; mi < 4; ++mi) {
#pragma unroll
        for (int ni = 0; ni < 4; ++ni) {
            const int row = m0 + wm * 64 + mi * 16 + g;
            const int col = n0 + wn * 32 + ni * 8 + 2 * t;
            float* p0 = C + (size_t)row * CDIM + col;
            float* p1 = C + (size_t)(row + 8) * CDIM + col;
            if (MODE == 1) {
                const float b0v = bias[col], b1v = bias[col + 1];
                *reinterpret_cast<float2*>(p0) =
                    make_float2(acc[mi][ni][0] + b0v, acc[mi][ni][1] + b1v);
                *reinterpret_cast<float2*>(p1) =
                    make_float2(acc[mi][ni][2] + b0v, acc[mi][ni][3] + b1v);
            } else if (MODE == 3) {
                *reinterpret_cast<float2*>(p0) =
                    make_float2(acc[mi][ni][0], acc[mi][ni][1]);
                *reinterpret_cast<float2*>(p1) =
                    make_float2(acc[mi][ni][2], acc[mi][ni][3]);
            } else {
                *reinterpret_cast<float2*>(p0) =
                    make_float2(tf32r(acc[mi][ni][0]), tf32r(acc[mi][ni][1]));
                *reinterpret_cast<float2*>(p1) =
                    make_float2(tf32r(acc[mi][ni][2]), tf32r(acc[mi][ni][3]));
            }
        }
    }
}

// ---------------------------------------------------------------------------
// r_build (scalar SIMT, spill-proof; R15-proven structure):
// R_b[c, h*64+e] = sum_d Wq[h*64+d, c] * 0.125*F_b[h*64+d, h*64+e]
// Wq exact fp32. grid (256 c-chunks of 4, 16 h, 4 b), 256 threads.
// ---------------------------------------------------------------------------
__global__ __launch_bounds__(256, 1)
void r_build(const float* __restrict__ Wq)
{
    __shared__ float skv[64][64];
    __shared__ float swq[4][64];
    const int b  = blockIdx.z, h = blockIdx.y;
    const int c0 = blockIdx.x * 4;
    const int tid = threadIdx.x;
    const int cl = tid >> 6;        // 0..3
    const int e  = tid & 63;        // 0..63

    const float* F = g_f + (size_t)b * CDIM * CDIM;
    for (int i = tid; i < 4096; i += 256) {
        const int d = i >> 6, ee = i & 63;
        skv[d][ee] = 0.125f * F[(size_t)(h * 64 + d) * CDIM + h * 64 + ee];
    }
    swq[cl][e] = Wq[(size_t)(h * 64 + e) * CDIM + c0 + cl];
    __syncthreads();

    float acc = 0.f;
    for (int d = 0; d < 64; ++d)
        acc += swq[cl][d] * skv[d][e];

    g_r[(size_t)b * CDIM * CDIM + (size_t)(c0 + cl) * CDIM + h * 64 + e] = tf32r(acc);
}

extern "C" void kernel_launch(void* const* d_in, const int* in_sizes, int n_in,
                              void* d_out, int out_size)
{
    (void)in_sizes; (void)n_in; (void)out_size;
    const float* x  = (const float*)d_in[0];
    const float* Wq = (const float*)d_in[1];
    const float* Wk = (const float*)d_in[2];
    const float* Wv = (const float*)d_in[3];
    const float* Wo = (const float*)d_in[4];
    const float* bo = (const float*)d_in[5];
    float* out = (float*)d_out;

    // prepass: tf32-round X, Wk, Wv, Wo (Wq stays exact fp32 for r_build)
    round_tf32<<<(B4 * NSEQ * CDIM / 4) / 256, 256>>>(x, 0);
    round_tf32<<<(CDIM * CDIM / 4) / 256, 256>>>(Wk, 1);
    round_tf32<<<(CDIM * CDIM / 4) / 256, 256>>>(Wv, 2);
    round_tf32<<<(CDIM * CDIM / 4) / 256, 256>>>(Wo, 3);

    // XT = X^T per batch
    transp<<<dim3(CDIM / 32, NSEQ / 32, B4), 256>>>();

    // S upper tiles = XT @ XT^T (K=4096), raw; mirror + round in place
    sgemm_tri<<<dim3(8, 8, B4), 256>>>();
    s_mirror<<<dim3(CDIM * CDIM / 256, B4), 256>>>();

    // P = Wk @ S ; F = P @ Wv^T (full; diagonal blocks are the kv matrices)
    gemm_b<2><<<dim3(8, 8, B4), 256>>>(nullptr, nullptr);
    gemm_b<3><<<dim3(8, 8, B4), 256>>>(nullptr, nullptr);

    // R_b[c,he] = sum_d Wq[hd,c] * 0.125*F[hd, he]  (exact fp32 Wq)
    r_build<<<dim3(256, NH, B4), 256>>>(Wq);

    // Gt_b = Wo (contract he) R_b^T ; out = X @ Gt^T + bo
    gemm_b<0><<<dim3(8, 8, B4), 256>>>(nullptr, nullptr);
    gemm_b<1><<<dim3(8, 32, B4), 256>>>(bo, out);
}